// round 13
// baseline (speedup 1.0000x reference)
#include <cuda_runtime.h>
#include <cuda_bf16.h>
#include <math.h>
#include <stdint.h>

#define BB 1024
#define DD 64
#define HH 128
#define NT 8            // j-tiles (128 each)
#define THREADS 256

#if defined(__CUDA_ARCH_FEAT_SM103_ALL) || defined(__CUDA_ARCH_FEAT_SM100_ALL) || \
    defined(__CUDA_ARCH_FEAT_SM101_ALL)
#define HAS_TCGEN05 1
#else
#define HAS_TCGEN05 0
#endif

// pair kernel dynamic smem layout (bytes)
#define OFF_A     0          // Wab^T bf16 image, 16384
#define OFF_A2    16384      // (Wj-Wd)^T bf16 image, 16384
#define OFF_BX    32768      // 2 x bf16 x_j tile image, 32768
#define OFF_B     65536      // 2 x |delta| bf16 [128j x 64k] SW128 (dbl-buf), 32768
#define OFF_SC    98304      // S partials f32 [2][128], 1024
#define OFF_MBAR  99328      // 2 mbarriers
#define OFF_TPTR  99344
#define SMEM_TOTAL 99360

// idesc: dtype=F32, a=BF16, b=BF16, N=128, M=128 (proven R7/R9)
#define IDESC ((1u << 4) | (1u << 7) | (1u << 10) | ((HH / 8) << 17) | (8u << 24))

// Scratch
__device__ __align__(16) float g_T1[BB * HH];
__device__ __align__(16) float g_S[BB * HH];
__device__ float g_tau[BB];
// bf16 SW128 SMEM-images, built once by image_kernel
__device__ __align__(16) uint32_t g_Aimg[4096];    // 16KB
__device__ __align__(16) uint32_t g_A2img[4096];   // 16KB
__device__ __align__(16) uint32_t g_Ximg[32768];   // 8 tile-images x 16KB

__device__ __forceinline__ uint32_t pack_bf2(float lo, float hi) {
  __nv_bfloat162 v = __floats2bfloat162_rn(lo, hi);
  return *(uint32_t*)&v;
}
__device__ __forceinline__ uint32_t habs_sub2(uint32_t a, uint32_t b) {
  __nv_bfloat162 av = *(__nv_bfloat162*)&a, bv = *(__nv_bfloat162*)&b;
  __nv_bfloat162 r = __habs2(__hsub2(av, bv));
  return *(uint32_t*)&r;
}
__device__ __host__ __forceinline__ uint32_t sw128(uint32_t o) {
  return o ^ ((o >> 3) & 0x70);
}
__device__ __forceinline__ uint64_t smem_desc(uint32_t addr) {
  return (2ull << 61) | (1ull << 46) | (64ull << 32) | (1ull << 16) |
         ((uint64_t)(addr >> 4) & 0x3FFF);
}
__device__ __forceinline__ void cp16(uint32_t smem_dst, const void* gsrc) {
  asm volatile("cp.async.cg.shared.global [%0], [%1], 16;" ::"r"(smem_dst),
               "l"(gsrc)
               : "memory");
}

#if HAS_TCGEN05
__device__ __forceinline__ void mma_f16_ss(uint32_t d, uint64_t ad, uint64_t bd,
                                           uint32_t idesc, bool accum) {
  uint32_t en = accum ? 1u : 0u;
  asm volatile(
      "{\n\t.reg .pred p;\n\tsetp.ne.u32 p, %5, 0;\n\t"
      "tcgen05.mma.cta_group::1.kind::f16 [%0], %1, %2, %3, {%4,%4,%4,%4}, "
      "p;\n\t}"
      :: "r"(d), "l"(ad), "l"(bd), "r"(idesc), "r"(0u), "r"(en)
      : "memory");
}
__device__ __forceinline__ void mbar_wait(uint32_t mbar, int parity) {
  asm volatile(
      "{\n\t.reg .pred P;\n\t"
      "WL%=:\n\t"
      "mbarrier.try_wait.parity.acquire.cta.shared::cta.b64 P, [%0], %1, "
      "0x989680;\n\t"
      "@P bra WD%=;\n\t"
      "bra WL%=;\n\t"
      "WD%=:\n\t}"
      :: "r"(mbar), "r"((uint32_t)parity)
      : "memory");
}
#define LDTM_X16(r, a)                                                       \
  asm volatile(                                                              \
      "tcgen05.ld.sync.aligned.32x32b.x16.b32 "                              \
      "{%0,%1,%2,%3,%4,%5,%6,%7,%8,%9,%10,%11,%12,%13,%14,%15}, [%16];"      \
      : "=r"((r)[0]), "=r"((r)[1]), "=r"((r)[2]), "=r"((r)[3]),              \
        "=r"((r)[4]), "=r"((r)[5]), "=r"((r)[6]), "=r"((r)[7]),              \
        "=r"((r)[8]), "=r"((r)[9]), "=r"((r)[10]), "=r"((r)[11]),            \
        "=r"((r)[12]), "=r"((r)[13]), "=r"((r)[14]), "=r"((r)[15])           \
      : "r"(a))
#endif  // HAS_TCGEN05

// ---------------------------------------------------------------------------
// Kernel 1: one launch, grid 296.
//  blocks 0..31  : g_Ximg (x -> bf16 SW128 tile images)
//  blocks 32..35 : g_Aimg (Wab^T)
//  blocks 36..39 : g_A2img ((Wj-Wd)^T)
//  blocks 40..295: T1 + tau, 4 rows/CTA (grid-starvation fix)
// ---------------------------------------------------------------------------
__global__ __launch_bounds__(THREADS) void image_kernel(
    const float* __restrict__ x, const float* __restrict__ W1,
    const float* __restrict__ b1, const float* __restrict__ Wt,
    const float* __restrict__ bt) {
  const int b = blockIdx.x, t = threadIdx.x;
  if (b < 32) {  // g_Ximg
#pragma unroll
    for (int q = 0; q < 2; q++) {
      const int e = b * 512 + t + q * THREADS;
      const int j = e >> 4, kp = e & 15, k = kp * 4;
      const float4 x4 = *(const float4*)&x[(size_t)j * DD + k];
      uint2 o;
      o.x = pack_bf2(x4.x, x4.y);
      o.y = pack_bf2(x4.z, x4.w);
      *(uint2*)((char*)g_Ximg + (j >> 7) * 16384 +
                sw128((uint32_t)((j & 127) * 128 + kp * 8))) = o;
    }
  } else if (b < 36) {  // g_Aimg: Wab^T
#pragma unroll
    for (int q = 0; q < 2; q++) {
      const int e = (b - 32) * 512 + t + q * THREADS;
      const int m = e >> 4, kp = e & 15, k = kp * 4;
      uint2 o;
      o.x = pack_bf2(W1[(size_t)(3 * DD + k) * HH + m],
                     W1[(size_t)(3 * DD + k + 1) * HH + m]);
      o.y = pack_bf2(W1[(size_t)(3 * DD + k + 2) * HH + m],
                     W1[(size_t)(3 * DD + k + 3) * HH + m]);
      *(uint2*)((char*)g_Aimg + sw128((uint32_t)(m * 128 + kp * 8))) = o;
    }
  } else if (b < 40) {  // g_A2img: (Wj - Wd)^T
#pragma unroll
    for (int q = 0; q < 2; q++) {
      const int e = (b - 36) * 512 + t + q * THREADS;
      const int m = e >> 4, kp = e & 15, k = kp * 4;
      uint2 o;
      o.x = pack_bf2(
          W1[(size_t)(DD + k) * HH + m] - W1[(size_t)(2 * DD + k) * HH + m],
          W1[(size_t)(DD + k + 1) * HH + m] -
              W1[(size_t)(2 * DD + k + 1) * HH + m]);
      o.y = pack_bf2(
          W1[(size_t)(DD + k + 2) * HH + m] -
              W1[(size_t)(2 * DD + k + 2) * HH + m],
          W1[(size_t)(DD + k + 3) * HH + m] -
              W1[(size_t)(2 * DD + k + 3) * HH + m]);
      *(uint2*)((char*)g_A2img + sw128((uint32_t)(m * 128 + kp * 8))) = o;
    }
  } else {  // T1 + tau, 4 rows per CTA
    __shared__ float xr[4 * DD];
    const int i0 = (b - 40) * 4;
    if (t < 4 * DD) xr[t] = x[(size_t)i0 * DD + t];
    __syncthreads();

    const int h = t & 127, io = t >> 7;
    const float base = b1[h];
#pragma unroll
    for (int q = 0; q < 2; q++) {
      const int row = io + q * 2;
      float a = base;
#pragma unroll 8
      for (int d = 0; d < DD; ++d)
        a += xr[row * DD + d] * (W1[d * HH + h] + W1[(2 * DD + d) * HH + h]);
      g_T1[(size_t)(i0 + row) * HH + h] = a;
    }
    if (t < 4) {
      float z = bt[0];
#pragma unroll 8
      for (int d = 0; d < DD; ++d) z += xr[t * DD + d] * Wt[d];
      const float sp = (z > 20.f) ? z : log1pf(expf(z));
      g_tau[i0 + t] = fmaxf(sp, 0.01f) + 1.0f;
    }
  }
}

// ---------------------------------------------------------------------------
// Kernel 2: tcgen05 pair-GEMM, software-pipelined: epilogue(t-1) overlaps
// MMA(t). One i per CTA (grid 1024), B + BX + TMEM D double-buffered,
// 2 alternating mbarriers (single-parity deadlock avoidance).
//   D[h][j] = Wab^T @ |x_i - x_j|^T + (Wj-Wd)^T @ x_j^T
//   S[i,h]  = sum_j relu(D + T1[i,h])
// ---------------------------------------------------------------------------
__global__ __launch_bounds__(THREADS, 2)
void pair_kernel(const float* __restrict__ x, const float* __restrict__ W1) {
#if HAS_TCGEN05
  extern __shared__ __align__(16) char smem[];
  float* Sc = (float*)(smem + OFF_SC);  // [2][128]
  const uint32_t su = (uint32_t)__cvta_generic_to_shared(smem);

  const int t = threadIdx.x;
  const int w = t >> 5, lane = t & 31;
  const int sub = w & 3, ch = w >> 2;
  const int h = sub * 32 + lane;
  const int i = blockIdx.x;
  const int kp = t & 15;

  if (w == 0) {
    asm volatile(
        "tcgen05.alloc.cta_group::1.sync.aligned.shared::cta.b32 [%0], %1;"
        :: "r"(su + OFF_TPTR), "r"(256u)
        : "memory");
    asm volatile("tcgen05.relinquish_alloc_permit.cta_group::1.sync.aligned;");
  }
  if (t == 0) {
    asm volatile("mbarrier.init.shared.b64 [%0], %1;" ::"r"(su + OFF_MBAR),
                 "r"(1u)
                 : "memory");
    asm volatile("mbarrier.init.shared.b64 [%0], %1;" ::"r"(su + OFF_MBAR + 8),
                 "r"(1u)
                 : "memory");
  }

  // stage A, A2 images + BX tile 0 (contiguous, coalesced)
#pragma unroll
  for (int r = 0; r < 4; r++) {
    const int e = t + r * THREADS;
    cp16(su + OFF_A + (uint32_t)e * 16, (const char*)g_Aimg + e * 16);
    cp16(su + OFF_A2 + (uint32_t)e * 16, (const char*)g_A2img + e * 16);
    cp16(su + OFF_BX + (uint32_t)e * 16, (const char*)g_Ximg + e * 16);
  }
  asm volatile("cp.async.commit_group;" ::: "memory");

  // x_i bf16 slice + T1 column (precomputed)
  const uint2 xib = *(const uint2*)((const char*)g_Ximg + (i >> 7) * 16384 +
                                    sw128((uint32_t)((i & 127) * 128 + kp * 8)));
  const float t1v = g_T1[(size_t)i * HH + h];
  float acc = 0.f;
  __syncthreads();
  uint32_t tmem;
  asm volatile("ld.shared.b32 %0, [%1];" : "=r"(tmem) : "r"(su + OFF_TPTR));

  const uint64_t adesc = smem_desc(su + OFF_A);
  const uint64_t a2desc = smem_desc(su + OFF_A2);

  for (int tt = 0; tt < NT; tt++) {
    const int cur = tt & 1;
    // BX(tt) (and B-buffer availability via the t-2 epilogue path) ready
    asm volatile("cp.async.wait_group 0;" ::: "memory");
    __syncthreads();

    // build |delta| tile tt into Bbuf[cur] (from BX[cur] + regs)
#pragma unroll
    for (int r = 0; r < 8; r++) {
      const int e = t + r * THREADS;
      const int j = e >> 4;
      const uint32_t so = sw128((uint32_t)(j * 128 + kp * 8));
      const uint2 bx = *(const uint2*)(smem + OFF_BX + cur * 16384 + so);
      uint2 o;
      o.x = habs_sub2(bx.x, xib.x);
      o.y = habs_sub2(bx.y, xib.y);
      *(uint2*)(smem + OFF_B + cur * 16384 + so) = o;
    }
    asm volatile("fence.proxy.async.shared::cta;" ::: "memory");
    __syncthreads();

    // MMA(tt) -> Dbuf[cur], commit to mbar[cur]
    if (t == 0) {
      const uint64_t bdesc = smem_desc(su + OFF_B + cur * 16384);
      const uint64_t bxdesc = smem_desc(su + OFF_BX + cur * 16384);
#pragma unroll
      for (int ks = 0; ks < 4; ks++)
        mma_f16_ss(tmem + cur * 128, adesc + ks * 2, bdesc + ks * 2, IDESC,
                   ks > 0);
#pragma unroll
      for (int ks = 0; ks < 4; ks++)
        mma_f16_ss(tmem + cur * 128, a2desc + ks * 2, bxdesc + ks * 2, IDESC,
                   true);
      asm volatile(
          "tcgen05.commit.cta_group::1.mbarrier::arrive::one.shared::cluster."
          "b64 [%0];" ::"r"(su + OFF_MBAR + (uint32_t)cur * 8)
          : "memory");
    }

    // epilogue(tt-1): overlaps MMA(tt)
    if (tt > 0) {
      const int pb = (tt - 1) & 1;
      mbar_wait(su + OFF_MBAR + (uint32_t)pb * 8, ((tt - 1) >> 1) & 1);
      asm volatile("tcgen05.fence::after_thread_sync;" ::: "memory");
#pragma unroll
      for (int c = 0; c < 4; c++) {
        uint32_t Dr[16];
        LDTM_X16(Dr, tmem + pb * 128 + c * 32 + ch * 16);
        asm volatile("tcgen05.wait::ld.sync.aligned;" ::: "memory");
        float a = 0.f;
#pragma unroll
        for (int r = 0; r < 16; r++)
          a += fmaxf(__uint_as_float(Dr[r]) + t1v, 0.f);
        acc += a;
      }
      asm volatile("tcgen05.fence::before_thread_sync;" ::: "memory");
      // MMA(tt-1) done -> safe to overwrite BX[(tt+1)&1] (= BX[pb])
      if (tt + 1 < NT) {
#pragma unroll
        for (int r = 0; r < 4; r++) {
          const int e = t + r * THREADS;
          cp16(su + OFF_BX + (uint32_t)(pb * 16384 + e * 16),
               (const char*)g_Ximg + (tt + 1) * 16384 + e * 16);
        }
      }
      asm volatile("cp.async.commit_group;" ::: "memory");
    } else {
      // tt==0: BX[1] unused yet; prefetch tile 1 without waiting
#pragma unroll
      for (int r = 0; r < 4; r++) {
        const int e = t + r * THREADS;
        cp16(su + OFF_BX + (uint32_t)(16384 + e * 16),
             (const char*)g_Ximg + 16384 + e * 16);
      }
      asm volatile("cp.async.commit_group;" ::: "memory");
    }
  }

  // final epilogue: tile NT-1
  {
    const int pb = (NT - 1) & 1;
    mbar_wait(su + OFF_MBAR + (uint32_t)pb * 8, ((NT - 1) >> 1) & 1);
    asm volatile("tcgen05.fence::after_thread_sync;" ::: "memory");
#pragma unroll
    for (int c = 0; c < 4; c++) {
      uint32_t Dr[16];
      LDTM_X16(Dr, tmem + pb * 128 + c * 32 + ch * 16);
      asm volatile("tcgen05.wait::ld.sync.aligned;" ::: "memory");
      float a = 0.f;
#pragma unroll
      for (int r = 0; r < 16; r++)
        a += fmaxf(__uint_as_float(Dr[r]) + t1v, 0.f);
      acc += a;
    }
    asm volatile("tcgen05.fence::before_thread_sync;" ::: "memory");
  }
  __syncthreads();

  // combine col-halves; single writer per (i,h)
  Sc[ch * 128 + h] = acc;
  __syncthreads();
  if (t < HH) g_S[(size_t)i * HH + t] = Sc[t] + Sc[128 + t];
  __syncthreads();
  if (t == 0) {
    asm volatile("mbarrier.inval.shared.b64 [%0];" ::"r"(su + OFF_MBAR)
                 : "memory");
    asm volatile("mbarrier.inval.shared.b64 [%0];" ::"r"(su + OFF_MBAR + 8)
                 : "memory");
  }
  __syncthreads();
  if (w == 0)
    asm volatile("tcgen05.dealloc.cta_group::1.sync.aligned.b32 %0, %1;" ::"r"(
                     tmem),
                 "r"(256u));
#else
  // Fallback for the generic compute_103 PTX pass (correctness-only; never
  // selected on GB300 -- the sm_103a cubin runs).
  const int t = threadIdx.x;
  const int i = blockIdx.x;
  for (int h = t; h < HH; h += THREADS) {
    float wcol[DD], w2col[DD];
    for (int d = 0; d < DD; d++) {
      wcol[d] = W1[(size_t)(3 * DD + d) * HH + h];
      w2col[d] =
          W1[(size_t)(DD + d) * HH + h] - W1[(size_t)(2 * DD + d) * HH + h];
    }
    const float t1 = g_T1[(size_t)i * HH + h];
    float s = 0.f;
    for (int j = 0; j < BB; j++) {
      float ta = 0.f, t2 = 0.f;
      for (int d = 0; d < DD; d++) {
        ta += fabsf(x[(size_t)i * DD + d] - x[(size_t)j * DD + d]) * wcol[d];
        t2 += x[(size_t)j * DD + d] * w2col[d];
      }
      s += fmaxf(ta + t1 + t2, 0.f);
    }
    g_S[(size_t)i * HH + h] = s;
  }
#endif
}

// ---------------------------------------------------------------------------
// Kernel 3: head + layernorm, 4 rows/CTA (shares W2/Wa reads across rows).
// ---------------------------------------------------------------------------
__global__ __launch_bounds__(512) void head_kernel(
    const float* __restrict__ x, const float* __restrict__ W2,
    const float* __restrict__ b2, const float* __restrict__ Wa,
    const float* __restrict__ ba, const float* __restrict__ Wr,
    const float* __restrict__ br, const float* __restrict__ gamma,
    const float* __restrict__ beta, float* __restrict__ out) {
  __shared__ float S_s[4][HH], hm_s[4][HH], xi[4][DD];
  __shared__ float red[4][4];
  const int t = threadIdx.x;
  const int rr = t >> 7, h = t & 127;
  const int wg = (t >> 5) & 3, lane = t & 31;
  const int i = blockIdx.x * 4 + rr;

  if (h < DD) xi[rr][h] = x[(size_t)i * DD + h];
  S_s[rr][h] = g_S[(size_t)i * HH + h] * (1.0f / BB);
  __syncthreads();

  float acc = b2[h];
#pragma unroll 8
  for (int k = 0; k < HH; ++k) acc += S_s[rr][k] * W2[k * HH + h];
  hm_s[rr][h] = acc / g_tau[i];
  __syncthreads();

  float acc2 = ba[h];
#pragma unroll 8
  for (int k = 0; k < HH; ++k) acc2 += hm_s[rr][k] * Wa[k * HH + h];
  const float hv = fmaxf(acc2, 0.f);
  float a3 = br[h];
#pragma unroll 8
  for (int d = 0; d < DD; ++d) a3 += xi[rr][d] * Wr[d * HH + h];
  const float yv = hv + a3;

  float v = yv;
#pragma unroll
  for (int off = 16; off > 0; off >>= 1) v += __shfl_xor_sync(0xffffffffu, v, off);
  if (lane == 0) red[rr][wg] = v;
  __syncthreads();
  const float mu =
      (red[rr][0] + red[rr][1] + red[rr][2] + red[rr][3]) * (1.0f / HH);
  __syncthreads();
  const float dv = yv - mu;
  float v2 = dv * dv;
#pragma unroll
  for (int off = 16; off > 0; off >>= 1) v2 += __shfl_xor_sync(0xffffffffu, v2, off);
  if (lane == 0) red[rr][wg] = v2;
  __syncthreads();
  const float var =
      (red[rr][0] + red[rr][1] + red[rr][2] + red[rr][3]) * (1.0f / HH);

  out[(size_t)i * HH + h] = dv * rsqrtf(var + 1e-5f) * gamma[h] + beta[h];
}

// ---------------------------------------------------------------------------
// Inputs: 0:x 1:W1 2:b1 3:W2 4:b2 5:Wt 6:bt 7:Wa 8:ba 9:Wr 10:br 11:gamma 12:beta
// ---------------------------------------------------------------------------
extern "C" void kernel_launch(void* const* d_in, const int* in_sizes, int n_in,
                              void* d_out, int out_size) {
  const float* x     = (const float*)d_in[0];
  const float* W1    = (const float*)d_in[1];
  const float* b1    = (const float*)d_in[2];
  const float* W2    = (const float*)d_in[3];
  const float* b2    = (const float*)d_in[4];
  const float* Wt    = (const float*)d_in[5];
  const float* bt    = (const float*)d_in[6];
  const float* Wa    = (const float*)d_in[7];
  const float* ba    = (const float*)d_in[8];
  const float* Wr    = (const float*)d_in[9];
  const float* br    = (const float*)d_in[10];
  const float* gamma = (const float*)d_in[11];
  const float* beta  = (const float*)d_in[12];
  float* out = (float*)d_out;

  cudaFuncSetAttribute(pair_kernel, cudaFuncAttributeMaxDynamicSharedMemorySize,
                       SMEM_TOTAL);
  image_kernel<<<296, THREADS>>>(x, W1, b1, Wt, bt);
  pair_kernel<<<BB, THREADS, SMEM_TOTAL>>>(x, W1);
  head_kernel<<<BB / 4, 512>>>(x, W2, b2, Wa, ba, Wr, br, gamma, beta, out);
}

// round 14
// speedup vs baseline: 1.1049x; 1.1049x over previous
#include <cuda_runtime.h>
#include <cuda_bf16.h>
#include <math.h>
#include <stdint.h>

#define BB 1024
#define DD 64
#define HH 128
#define IB 2            // i's per CTA
#define NT 8            // j-tiles (128 each)
#define THREADS 256

#if defined(__CUDA_ARCH_FEAT_SM103_ALL) || defined(__CUDA_ARCH_FEAT_SM100_ALL) || \
    defined(__CUDA_ARCH_FEAT_SM101_ALL)
#define HAS_TCGEN05 1
#else
#define HAS_TCGEN05 0
#endif

// pair kernel dynamic smem layout (bytes)
#define OFF_A     0          // Wab^T bf16 image, 16384
#define OFF_A2    16384      // (Wj-Wd)^T bf16 image, 16384
#define OFF_BX    32768      // 2 x bf16 x_j tile image, 32768
#define OFF_B     65536      // 2 x |delta| bf16 [128j x 64k] SW128, 32768
#define OFF_SC    98304      // S partials f32 [2][2][128], 2048
#define OFF_MBAR  100352     // 2 mbarriers
#define OFF_TPTR  100368
#define SMEM_TOTAL 100384

// idesc: dtype=F32, a=BF16, b=BF16, N=128, M=128 (proven R7/R9/R12)
#define IDESC ((1u << 4) | (1u << 7) | (1u << 10) | ((HH / 8) << 17) | (8u << 24))

// Scratch
__device__ __align__(16) float g_T1[BB * HH];
__device__ __align__(16) float g_S[BB * HH];
__device__ float g_tau[BB];
// bf16 SW128 SMEM-images, built once by image_kernel
__device__ __align__(16) uint32_t g_Aimg[4096];    // 16KB
__device__ __align__(16) uint32_t g_A2img[4096];   // 16KB
__device__ __align__(16) uint32_t g_Ximg[32768];   // 8 tile-images x 16KB

__device__ __forceinline__ uint32_t pack_bf2(float lo, float hi) {
  __nv_bfloat162 v = __floats2bfloat162_rn(lo, hi);
  return *(uint32_t*)&v;
}
__device__ __forceinline__ uint32_t habs_sub2(uint32_t a, uint32_t b) {
  __nv_bfloat162 av = *(__nv_bfloat162*)&a, bv = *(__nv_bfloat162*)&b;
  __nv_bfloat162 r = __habs2(__hsub2(av, bv));
  return *(uint32_t*)&r;
}
__device__ __host__ __forceinline__ uint32_t sw128(uint32_t o) {
  return o ^ ((o >> 3) & 0x70);
}
__device__ __forceinline__ uint64_t smem_desc(uint32_t addr) {
  return (2ull << 61) | (1ull << 46) | (64ull << 32) | (1ull << 16) |
         ((uint64_t)(addr >> 4) & 0x3FFF);
}
__device__ __forceinline__ void cp16(uint32_t smem_dst, const void* gsrc) {
  asm volatile("cp.async.cg.shared.global [%0], [%1], 16;" ::"r"(smem_dst),
               "l"(gsrc)
               : "memory");
}

#if HAS_TCGEN05
__device__ __forceinline__ void mma_f16_ss(uint32_t d, uint64_t ad, uint64_t bd,
                                           uint32_t idesc, bool accum) {
  uint32_t en = accum ? 1u : 0u;
  asm volatile(
      "{\n\t.reg .pred p;\n\tsetp.ne.u32 p, %5, 0;\n\t"
      "tcgen05.mma.cta_group::1.kind::f16 [%0], %1, %2, %3, {%4,%4,%4,%4}, "
      "p;\n\t}"
      :: "r"(d), "l"(ad), "l"(bd), "r"(idesc), "r"(0u), "r"(en)
      : "memory");
}
__device__ __forceinline__ void mbar_wait(uint32_t mbar, int parity) {
  asm volatile(
      "{\n\t.reg .pred P;\n\t"
      "WL%=:\n\t"
      "mbarrier.try_wait.parity.acquire.cta.shared::cta.b64 P, [%0], %1, "
      "0x989680;\n\t"
      "@P bra WD%=;\n\t"
      "bra WL%=;\n\t"
      "WD%=:\n\t}"
      :: "r"(mbar), "r"((uint32_t)parity)
      : "memory");
}
#define LDTM_X16(r, a)                                                       \
  asm volatile(                                                              \
      "tcgen05.ld.sync.aligned.32x32b.x16.b32 "                              \
      "{%0,%1,%2,%3,%4,%5,%6,%7,%8,%9,%10,%11,%12,%13,%14,%15}, [%16];"      \
      : "=r"((r)[0]), "=r"((r)[1]), "=r"((r)[2]), "=r"((r)[3]),              \
        "=r"((r)[4]), "=r"((r)[5]), "=r"((r)[6]), "=r"((r)[7]),              \
        "=r"((r)[8]), "=r"((r)[9]), "=r"((r)[10]), "=r"((r)[11]),            \
        "=r"((r)[12]), "=r"((r)[13]), "=r"((r)[14]), "=r"((r)[15])           \
      : "r"(a))
#endif  // HAS_TCGEN05

// ---------------------------------------------------------------------------
// Kernel 1: one launch, grid 104 (single wave).
//  blocks 0..31 : g_Ximg (x -> bf16 SW128 tile images)
//  blocks 32..35: g_Aimg (Wab^T)
//  blocks 36..39: g_A2img ((Wj-Wd)^T)
//  blocks 40..103: T1 + tau, 16 rows/CTA, Wsum staged once in smem.
// ---------------------------------------------------------------------------
__global__ __launch_bounds__(THREADS) void image_kernel(
    const float* __restrict__ x, const float* __restrict__ W1,
    const float* __restrict__ b1, const float* __restrict__ Wt,
    const float* __restrict__ bt) {
  const int b = blockIdx.x, t = threadIdx.x;
  if (b < 32) {  // g_Ximg
#pragma unroll
    for (int q = 0; q < 2; q++) {
      const int e = b * 512 + t + q * THREADS;
      const int j = e >> 4, kp = e & 15, k = kp * 4;
      const float4 x4 = *(const float4*)&x[(size_t)j * DD + k];
      uint2 o;
      o.x = pack_bf2(x4.x, x4.y);
      o.y = pack_bf2(x4.z, x4.w);
      *(uint2*)((char*)g_Ximg + (j >> 7) * 16384 +
                sw128((uint32_t)((j & 127) * 128 + kp * 8))) = o;
    }
  } else if (b < 36) {  // g_Aimg: Wab^T
#pragma unroll
    for (int q = 0; q < 2; q++) {
      const int e = (b - 32) * 512 + t + q * THREADS;
      const int m = e >> 4, kp = e & 15, k = kp * 4;
      uint2 o;
      o.x = pack_bf2(W1[(size_t)(3 * DD + k) * HH + m],
                     W1[(size_t)(3 * DD + k + 1) * HH + m]);
      o.y = pack_bf2(W1[(size_t)(3 * DD + k + 2) * HH + m],
                     W1[(size_t)(3 * DD + k + 3) * HH + m]);
      *(uint2*)((char*)g_Aimg + sw128((uint32_t)(m * 128 + kp * 8))) = o;
    }
  } else if (b < 40) {  // g_A2img: (Wj - Wd)^T
#pragma unroll
    for (int q = 0; q < 2; q++) {
      const int e = (b - 36) * 512 + t + q * THREADS;
      const int m = e >> 4, kp = e & 15, k = kp * 4;
      uint2 o;
      o.x = pack_bf2(
          W1[(size_t)(DD + k) * HH + m] - W1[(size_t)(2 * DD + k) * HH + m],
          W1[(size_t)(DD + k + 1) * HH + m] -
              W1[(size_t)(2 * DD + k + 1) * HH + m]);
      o.y = pack_bf2(
          W1[(size_t)(DD + k + 2) * HH + m] -
              W1[(size_t)(2 * DD + k + 2) * HH + m],
          W1[(size_t)(DD + k + 3) * HH + m] -
              W1[(size_t)(2 * DD + k + 3) * HH + m]);
      *(uint2*)((char*)g_A2img + sw128((uint32_t)(m * 128 + kp * 8))) = o;
    }
  } else {  // T1 + tau, 16 rows per CTA, Wsum staged in smem
    __shared__ float Wsum[DD * HH];  // 32KB
    __shared__ float xr[16 * DD];    // 4KB
    const int i0 = (b - 40) * 16;
#pragma unroll
    for (int r = 0; r < 32; r++) {
      const int e = t + r * THREADS;  // e = d*128 + h
      Wsum[e] = W1[e] + W1[2 * DD * HH + e];
    }
#pragma unroll
    for (int r = 0; r < 4; r++)
      xr[t + r * THREADS] = x[(size_t)i0 * DD + t + r * THREADS];
    __syncthreads();

    const int h = t & 127, io = t >> 7;
    const float base = b1[h];
#pragma unroll
    for (int q = 0; q < 8; q++) {
      const int row = io + q * 2;
      float a = base;
#pragma unroll 8
      for (int d = 0; d < DD; ++d) a += xr[row * DD + d] * Wsum[d * HH + h];
      g_T1[(size_t)(i0 + row) * HH + h] = a;
    }
    if (t < 16) {
      float z = bt[0];
#pragma unroll 8
      for (int d = 0; d < DD; ++d) z += xr[t * DD + d] * Wt[d];
      const float sp = (z > 20.f) ? z : log1pf(expf(z));
      g_tau[i0 + t] = fmaxf(sp, 0.01f) + 1.0f;
    }
  }
}

// ---------------------------------------------------------------------------
// Kernel 2: tcgen05 pair-GEMM (R12 structure, IB=2, grid 512) with SPLIT
// COMMITS: MMA(i0)->mbar0, MMA(i1)->mbar1; epilogue(i0) overlaps MMA(i1).
//   D[h][j] = Wab^T @ |x_i - x_j|^T + (Wj-Wd)^T @ x_j^T
//   S[i,h]  = sum_j relu(D + T1[i,h])
// ---------------------------------------------------------------------------
__global__ __launch_bounds__(THREADS, 2)
void pair_kernel(const float* __restrict__ x, const float* __restrict__ W1) {
#if HAS_TCGEN05
  extern __shared__ __align__(16) char smem[];
  float* Sc = (float*)(smem + OFF_SC);  // [2][2][128]
  const uint32_t su = (uint32_t)__cvta_generic_to_shared(smem);

  const int t = threadIdx.x;
  const int w = t >> 5, lane = t & 31;
  const int sub = w & 3, ch = w >> 2;
  const int h = sub * 32 + lane;
  const int i0 = blockIdx.x * IB;
  const int kp = t & 15;

  if (w == 0) {
    asm volatile(
        "tcgen05.alloc.cta_group::1.sync.aligned.shared::cta.b32 [%0], %1;"
        :: "r"(su + OFF_TPTR), "r"(256u)
        : "memory");
    asm volatile("tcgen05.relinquish_alloc_permit.cta_group::1.sync.aligned;");
  }
  if (t == 0) {
    asm volatile("mbarrier.init.shared.b64 [%0], %1;" ::"r"(su + OFF_MBAR),
                 "r"(1u)
                 : "memory");
    asm volatile("mbarrier.init.shared.b64 [%0], %1;" ::"r"(su + OFF_MBAR + 8),
                 "r"(1u)
                 : "memory");
  }

  // stage A, A2 images + BX tile 0 (contiguous, coalesced)
#pragma unroll
  for (int r = 0; r < 4; r++) {
    const int e = t + r * THREADS;
    cp16(su + OFF_A + (uint32_t)e * 16, (const char*)g_Aimg + e * 16);
    cp16(su + OFF_A2 + (uint32_t)e * 16, (const char*)g_A2img + e * 16);
    cp16(su + OFF_BX + (uint32_t)e * 16, (const char*)g_Ximg + e * 16);
  }
  asm volatile("cp.async.commit_group;" ::: "memory");

  // x_i bf16 slice + T1 columns (precomputed)
  uint2 xib[IB];
  float t1v[IB], acc[IB];
#pragma unroll
  for (int ii = 0; ii < IB; ii++) {
    const int gi = i0 + ii;
    xib[ii] = *(const uint2*)((const char*)g_Ximg + (gi >> 7) * 16384 +
                              sw128((uint32_t)((gi & 127) * 128 + kp * 8)));
    t1v[ii] = g_T1[(size_t)gi * HH + h];
    acc[ii] = 0.f;
  }
  __syncthreads();
  uint32_t tmem;
  asm volatile("ld.shared.b32 %0, [%1];" : "=r"(tmem) : "r"(su + OFF_TPTR));

  const uint64_t adesc = smem_desc(su + OFF_A);
  const uint64_t a2desc = smem_desc(su + OFF_A2);

  for (int tt = 0; tt < NT; tt++) {
    const int cur = tt & 1;
    if (tt + 1 < NT) {
#pragma unroll
      for (int r = 0; r < 4; r++) {
        const int e = t + r * THREADS;
        cp16(su + OFF_BX + (uint32_t)((cur ^ 1) * 16384 + e * 16),
             (const char*)g_Ximg + (tt + 1) * 16384 + e * 16);
      }
    }
    asm volatile("cp.async.commit_group;" ::: "memory");
    asm volatile("cp.async.wait_group 1;" ::: "memory");  // BX(tt) ready
    __syncthreads();

    // build |delta| tiles in bf16, all from smem
#pragma unroll
    for (int r = 0; r < 8; r++) {
      const int e = t + r * THREADS;
      const int j = e >> 4;
      const uint32_t so = sw128((uint32_t)(j * 128 + kp * 8));
      const uint2 bx = *(const uint2*)(smem + OFF_BX + cur * 16384 + so);
#pragma unroll
      for (int ii = 0; ii < IB; ii++) {
        uint2 o;
        o.x = habs_sub2(bx.x, xib[ii].x);
        o.y = habs_sub2(bx.y, xib[ii].y);
        *(uint2*)(smem + OFF_B + ii * 16384 + so) = o;
      }
    }
    asm volatile("fence.proxy.async.shared::cta;" ::: "memory");
    __syncthreads();

    // split commits: MMA(i0)->mbar0, MMA(i1)->mbar1
    if (t == 0) {
      const uint64_t bxdesc = smem_desc(su + OFF_BX + cur * 16384);
#pragma unroll
      for (int ii = 0; ii < IB; ii++) {
        const uint64_t bdesc = smem_desc(su + OFF_B + ii * 16384);
#pragma unroll
        for (int ks = 0; ks < 4; ks++)
          mma_f16_ss(tmem + ii * 128, adesc + ks * 2, bdesc + ks * 2, IDESC,
                     ks > 0);
#pragma unroll
        for (int ks = 0; ks < 4; ks++)
          mma_f16_ss(tmem + ii * 128, a2desc + ks * 2, bxdesc + ks * 2, IDESC,
                     true);
        asm volatile(
            "tcgen05.commit.cta_group::1.mbarrier::arrive::one.shared::cluster."
            "b64 [%0];" ::"r"(su + OFF_MBAR + (uint32_t)ii * 8)
            : "memory");
      }
    }

    // epilogue(i0) overlaps MMA(i1); then epilogue(i1)
#pragma unroll
    for (int ii = 0; ii < IB; ii++) {
      mbar_wait(su + OFF_MBAR + (uint32_t)ii * 8, tt & 1);
      asm volatile("tcgen05.fence::after_thread_sync;" ::: "memory");
#pragma unroll
      for (int c = 0; c < 4; c++) {
        uint32_t Dr[16];
        LDTM_X16(Dr, tmem + ii * 128 + c * 32 + ch * 16);
        asm volatile("tcgen05.wait::ld.sync.aligned;" ::: "memory");
        float a = 0.f;
#pragma unroll
        for (int r = 0; r < 16; r++)
          a += fmaxf(__uint_as_float(Dr[r]) + t1v[ii], 0.f);
        acc[ii] += a;
      }
    }
    asm volatile("tcgen05.fence::before_thread_sync;" ::: "memory");
    __syncthreads();  // LDTM + BX reads done before next build/MMA
  }

  // combine col-halves; single writer per (i,h)
#pragma unroll
  for (int ii = 0; ii < IB; ii++) Sc[(ii * 2 + ch) * 128 + h] = acc[ii];
  __syncthreads();
  if (t < HH) {
#pragma unroll
    for (int ii = 0; ii < IB; ii++)
      g_S[(size_t)(i0 + ii) * HH + t] =
          Sc[(ii * 2 + 0) * 128 + t] + Sc[(ii * 2 + 1) * 128 + t];
  }
  __syncthreads();
  if (t == 0) {
    asm volatile("mbarrier.inval.shared.b64 [%0];" ::"r"(su + OFF_MBAR)
                 : "memory");
    asm volatile("mbarrier.inval.shared.b64 [%0];" ::"r"(su + OFF_MBAR + 8)
                 : "memory");
  }
  __syncthreads();
  if (w == 0)
    asm volatile("tcgen05.dealloc.cta_group::1.sync.aligned.b32 %0, %1;" ::"r"(
                     tmem),
                 "r"(256u));
#else
  // Fallback for the generic compute_103 PTX pass (correctness-only; never
  // selected on GB300 -- the sm_103a cubin runs).
  const int t = threadIdx.x;
  const int h = t & 127;
  const int io = t >> 7;
  const int i = blockIdx.x * IB + io;
  float wcol[DD], w2col[DD];
  for (int d = 0; d < DD; d++) {
    wcol[d] = W1[(size_t)(3 * DD + d) * HH + h];
    w2col[d] = W1[(size_t)(DD + d) * HH + h] - W1[(size_t)(2 * DD + d) * HH + h];
  }
  const float t1 = g_T1[(size_t)i * HH + h];
  float s = 0.f;
  for (int j = 0; j < BB; j++) {
    float ta = 0.f, t2 = 0.f;
    for (int d = 0; d < DD; d++) {
      ta += fabsf(x[(size_t)i * DD + d] - x[(size_t)j * DD + d]) * wcol[d];
      t2 += x[(size_t)j * DD + d] * w2col[d];
    }
    s += fmaxf(ta + t1 + t2, 0.f);
  }
  g_S[(size_t)i * HH + h] = s;
#endif
}

// ---------------------------------------------------------------------------
// Kernel 3: head + layernorm, 4 rows/CTA (shares W2/Wa reads across rows).
// ---------------------------------------------------------------------------
__global__ __launch_bounds__(512) void head_kernel(
    const float* __restrict__ x, const float* __restrict__ W2,
    const float* __restrict__ b2, const float* __restrict__ Wa,
    const float* __restrict__ ba, const float* __restrict__ Wr,
    const float* __restrict__ br, const float* __restrict__ gamma,
    const float* __restrict__ beta, float* __restrict__ out) {
  __shared__ float S_s[4][HH], hm_s[4][HH], xi[4][DD];
  __shared__ float red[4][4];
  const int t = threadIdx.x;
  const int rr = t >> 7, h = t & 127;
  const int wg = (t >> 5) & 3, lane = t & 31;
  const int i = blockIdx.x * 4 + rr;

  if (h < DD) xi[rr][h] = x[(size_t)i * DD + h];
  S_s[rr][h] = g_S[(size_t)i * HH + h] * (1.0f / BB);
  __syncthreads();

  float acc = b2[h];
#pragma unroll 8
  for (int k = 0; k < HH; ++k) acc += S_s[rr][k] * W2[k * HH + h];
  hm_s[rr][h] = acc / g_tau[i];
  __syncthreads();

  float acc2 = ba[h];
#pragma unroll 8
  for (int k = 0; k < HH; ++k) acc2 += hm_s[rr][k] * Wa[k * HH + h];
  const float hv = fmaxf(acc2, 0.f);
  float a3 = br[h];
#pragma unroll 8
  for (int d = 0; d < DD; ++d) a3 += xi[rr][d] * Wr[d * HH + h];
  const float yv = hv + a3;

  float v = yv;
#pragma unroll
  for (int off = 16; off > 0; off >>= 1) v += __shfl_xor_sync(0xffffffffu, v, off);
  if (lane == 0) red[rr][wg] = v;
  __syncthreads();
  const float mu =
      (red[rr][0] + red[rr][1] + red[rr][2] + red[rr][3]) * (1.0f / HH);
  __syncthreads();
  const float dv = yv - mu;
  float v2 = dv * dv;
#pragma unroll
  for (int off = 16; off > 0; off >>= 1) v2 += __shfl_xor_sync(0xffffffffu, v2, off);
  if (lane == 0) red[rr][wg] = v2;
  __syncthreads();
  const float var =
      (red[rr][0] + red[rr][1] + red[rr][2] + red[rr][3]) * (1.0f / HH);

  out[(size_t)i * HH + h] = dv * rsqrtf(var + 1e-5f) * gamma[h] + beta[h];
}

// ---------------------------------------------------------------------------
// Inputs: 0:x 1:W1 2:b1 3:W2 4:b2 5:Wt 6:bt 7:Wa 8:ba 9:Wr 10:br 11:gamma 12:beta
// ---------------------------------------------------------------------------
extern "C" void kernel_launch(void* const* d_in, const int* in_sizes, int n_in,
                              void* d_out, int out_size) {
  const float* x     = (const float*)d_in[0];
  const float* W1    = (const float*)d_in[1];
  const float* b1    = (const float*)d_in[2];
  const float* W2    = (const float*)d_in[3];
  const float* b2    = (const float*)d_in[4];
  const float* Wt    = (const float*)d_in[5];
  const float* bt    = (const float*)d_in[6];
  const float* Wa    = (const float*)d_in[7];
  const float* ba    = (const float*)d_in[8];
  const float* Wr    = (const float*)d_in[9];
  const float* br    = (const float*)d_in[10];
  const float* gamma = (const float*)d_in[11];
  const float* beta  = (const float*)d_in[12];
  float* out = (float*)d_out;

  cudaFuncSetAttribute(pair_kernel, cudaFuncAttributeMaxDynamicSharedMemorySize,
                       SMEM_TOTAL);
  image_kernel<<<104, THREADS>>>(x, W1, b1, Wt, bt);
  pair_kernel<<<BB / IB, THREADS, SMEM_TOTAL>>>(x, W1);
  head_kernel<<<BB / 4, 512>>>(x, W2, b2, Wa, ba, Wr, br, gamma, beta, out);
}